// round 10
// baseline (speedup 1.0000x reference)
#include <cuda_runtime.h>
#include <math.h>

#define TT 100
#define BB 64
#define II 256
#define HH 512
#define H3 1536
#define H4 2048
#define NBLK 128          // persistent grid size (1 block/SM)
#define KC 16             // K split chunks (512/32)
#define BKC 32            // K per chunk

// float4-index permutation for stride-2 f4 read patterns (gx)
#define PF4(x) ((x) + ((x) >> 3))

// ---------------- scratch (device globals) ----------------
__device__ float g_WihP[II * H4];                 // packed: [k][ (n%512)*4 + n/512 ]
__device__ float g_WhhP[HH * H4];
__device__ float g_biasP[H4];
__device__ float g_Gx[(size_t)TT * BB * H4];      // packed gate pre-activations from input path
__device__ float g_h[(size_t)(TT + 1) * BB * HH]; // h history [t][b][h]
__device__ float g_f[(size_t)TT * BB * HH];
__device__ float g_d[(size_t)TT * BB * H3];       // later overwritten with w = d * suffix-prod(f)
__device__ float g_gpart[(size_t)KC * BB * H4];   // split-K partials [kc][m][packed n]
__device__ unsigned g_cnt_g[TT][8];               // partials-done counters per (t, nt)
__device__ unsigned g_cnt_c[TT][8];               // cells-done counters per (t, nt)

// ---------------- prep ----------------
__global__ void prep_kernel(const float* __restrict__ h0, const float* __restrict__ bih,
                            const float* __restrict__ bhh) {
    int i = blockIdx.x * blockDim.x + threadIdx.x;
    if (i < TT * 8) { (&g_cnt_g[0][0])[i] = 0u; (&g_cnt_c[0][0])[i] = 0u; }
    if (i < H4) g_biasP[(i & 511) * 4 + (i >> 9)] = bih[i] + bhh[i];
    if (i < BB * HH) g_h[i] = h0[i];
}

// ---------------- pack weights: in[2048][K] -> out[K][2048 packed] ----------------
__global__ void pack_w(const float* __restrict__ in, int K, int which) {
    __shared__ float s[32][33];
    int k0 = blockIdx.x * 32, n0 = blockIdx.y * 32;
    int tx = threadIdx.x, ty = threadIdx.y;
    for (int i = ty; i < 32; i += 8)
        s[i][tx] = in[(size_t)(n0 + i) * K + k0 + tx];
    __syncthreads();
    float* out = which ? g_WhhP : g_WihP;
    int g = n0 >> 9;
    int c = n0 & 511;
    for (int i = ty; i < 32; i += 8)
        out[(size_t)(k0 + i) * H4 + (c + tx) * 4 + g] = s[tx][i];
}

// ---------------- Gx = X[6400,256] @ WihP + biasP (packed out) — proven R6 scalar version ----------------
__global__ void gx_kernel(const float* __restrict__ X) {
    __shared__ __align__(16) float As[8][132];
    __shared__ __align__(16) float Bs[8][140];
    const int tid = threadIdx.x;
    const int n0 = blockIdx.x * 128;
    const int m0 = blockIdx.y * 128;
    const int tm = (tid >> 4) * 8, tn = (tid & 15) * 8;
    const int am = tid >> 1, ak = (tid & 1) * 4;
    const int bk = tid >> 5, bn_f4 = tid & 31;
    const int pn0 = PF4((tn >> 2));
    const int pn1 = PF4((tn >> 2) + 1);
    float acc[8][8] = {};
    for (int k0 = 0; k0 < II; k0 += 8) {
        float4 av = *(const float4*)(X + (size_t)(m0 + am) * II + k0 + ak);
        As[ak + 0][am] = av.x; As[ak + 1][am] = av.y; As[ak + 2][am] = av.z; As[ak + 3][am] = av.w;
        ((float4*)&Bs[bk][0])[PF4(bn_f4)] = *(const float4*)(g_WihP + (size_t)(k0 + bk) * H4 + n0 + bn_f4 * 4);
        __syncthreads();
#pragma unroll
        for (int u = 0; u < 8; u++) {
            float4 a0 = *(const float4*)&As[u][tm];
            float4 a1 = *(const float4*)&As[u][tm + 4];
            float4 b0 = ((const float4*)&Bs[u][0])[pn0];
            float4 b1 = ((const float4*)&Bs[u][0])[pn1];
            float aa[8] = {a0.x, a0.y, a0.z, a0.w, a1.x, a1.y, a1.z, a1.w};
            float bb[8] = {b0.x, b0.y, b0.z, b0.w, b1.x, b1.y, b1.z, b1.w};
#pragma unroll
            for (int i = 0; i < 8; i++)
#pragma unroll
                for (int j = 0; j < 8; j++)
                    acc[i][j] += aa[i] * bb[j];
        }
        __syncthreads();
    }
#pragma unroll
    for (int i = 0; i < 8; i++) {
        float* orow = g_Gx + (size_t)(m0 + tm + i) * H4 + n0 + tn;
        float4 v0 = make_float4(acc[i][0] + g_biasP[n0 + tn + 0], acc[i][1] + g_biasP[n0 + tn + 1],
                                acc[i][2] + g_biasP[n0 + tn + 2], acc[i][3] + g_biasP[n0 + tn + 3]);
        float4 v1 = make_float4(acc[i][4] + g_biasP[n0 + tn + 4], acc[i][5] + g_biasP[n0 + tn + 5],
                                acc[i][6] + g_biasP[n0 + tn + 6], acc[i][7] + g_biasP[n0 + tn + 7]);
        *(float4*)orow = v0;
        *(float4*)(orow + 4) = v1;
    }
}

// ---------------- persistent recurrent loop: R6 sync skeleton + acc[16][4] GEMM ----------------
// 128 blocks x 256 threads. Block (nt 0..7, kc 0..15): tile M=64, N=256 packed, K=32.
// Warps: 4 m-groups (Ma=16) x 2 n-groups; per u: 4 broadcast A + 1 B LDS.128 + 64 FFMA (ratio 2.0).
// Cell: block handles b in [kc*4,+4) x h-cols [nt*64,+64); c state in register.
__global__ void __launch_bounds__(256, 1)
loop_kernel(const float* __restrict__ c0, float* __restrict__ out_h, float* __restrict__ out_c) {
    __shared__ __align__(16) float Bs[BKC][256];   // weight chunk, plain rows (32 KB)
    __shared__ __align__(16) float As[BKC][68];    // h chunk [k][m]
    const int tid = threadIdx.x;
    const int nt = blockIdx.x & 7;
    const int kc = blockIdx.x >> 3;
    const int n0 = nt * 256;
    const int k0 = kc * BKC;

    // stage weight chunk once: 32 rows x 64 f4 = 2048 f4, 8 per thread
    {
        const float* wsrc = g_WhhP + (size_t)k0 * H4 + n0;
#pragma unroll
        for (int r = 0; r < 8; r++) {
            int e = r * 256 + tid;
            int kk = e >> 6;
            int nf4 = e & 63;
            *(float4*)&Bs[kk][nf4 * 4] = *(const float4*)(wsrc + (size_t)kk * H4 + nf4 * 4);
        }
    }

    const int wid = tid >> 5, lane = tid & 31;
    const int mb = (wid & 3) * 16;                // m base (warp-uniform)
    const int nf = (wid >> 2) * 32 + lane;        // f4 col in Bs (conflict-free, stride-1)
    // A staging map (conflict-free STS: warp writes one row, 32 consecutive cols)
    const int am = tid & 63, ak = (tid >> 6) * 8;
    // cell identity
    const int cb = kc * 4 + (tid >> 6);           // batch
    const int ch = nt * 64 + (tid & 63);          // global h col
    float creg = c0[(size_t)cb * HH + ch];
    const int nt_src = kc >> 1;                   // producer nt of this block's A k-chunk

    for (int t = 0; t < TT; t++) {
        // ---- wait for h[t] producers (skip t=0: prep wrote it) ----
        if (t > 0) {
            if (tid == 0) {
                volatile unsigned* p = &g_cnt_c[t - 1][nt_src];
                while (*p < 16u) __nanosleep(64);
                __threadfence();
            }
            __syncthreads();
        }

        // ---- load A chunk: h[t][64][k0..k0+32) -> As[k][m] ----
        const float* hsrc = g_h + (size_t)t * BB * HH;
        float4 v0 = __ldcg((const float4*)(hsrc + (size_t)am * HH + k0 + ak));
        float4 v1 = __ldcg((const float4*)(hsrc + (size_t)am * HH + k0 + ak + 4));
        As[ak + 0][am] = v0.x; As[ak + 1][am] = v0.y; As[ak + 2][am] = v0.z; As[ak + 3][am] = v0.w;
        As[ak + 4][am] = v1.x; As[ak + 5][am] = v1.y; As[ak + 6][am] = v1.z; As[ak + 7][am] = v1.w;

        // prefetch this step's Gx for the cell (independent of GEMM)
        float4 gx4 = __ldcg((const float4*)(g_Gx + ((size_t)t * BB + cb) * H4 + 4 * ch));
        __syncthreads();

        // ---- GEMM 64x256, K=32: acc[16][4] ----
        float acc[16][4] = {};
#pragma unroll 8
        for (int u = 0; u < BKC; u++) {
            float4 bv = *(const float4*)&Bs[u][nf * 4];
            float4 a0 = *(const float4*)&As[u][mb];         // broadcasts
            float4 a1 = *(const float4*)&As[u][mb + 4];
            float4 a2 = *(const float4*)&As[u][mb + 8];
            float4 a3 = *(const float4*)&As[u][mb + 12];
            float aa[16] = {a0.x, a0.y, a0.z, a0.w, a1.x, a1.y, a1.z, a1.w,
                            a2.x, a2.y, a2.z, a2.w, a3.x, a3.y, a3.z, a3.w};
#pragma unroll
            for (int i = 0; i < 16; i++) {
                acc[i][0] += aa[i] * bv.x;
                acc[i][1] += aa[i] * bv.y;
                acc[i][2] += aa[i] * bv.z;
                acc[i][3] += aa[i] * bv.w;
            }
        }
#pragma unroll
        for (int i = 0; i < 16; i++) {
            *(float4*)(g_gpart + ((size_t)kc * BB + mb + i) * H4 + n0 + nf * 4) =
                make_float4(acc[i][0], acc[i][1], acc[i][2], acc[i][3]);
        }

        // ---- signal partials done, wait for all 16 kc partials of our nt ----
        __threadfence();
        __syncthreads();                      // As also reused next step
        if (tid == 0) {
            atomicAdd(&g_cnt_g[t][nt], 1u);
            volatile unsigned* p = &g_cnt_g[t][nt];
            while (*p < 16u) __nanosleep(64);
            __threadfence();
        }
        __syncthreads();

        // ---- cell for (cb, ch) ----
        {
            float4 g4 = gx4;
#pragma unroll
            for (int q = 0; q < KC; q++) {
                float4 p = __ldcg((const float4*)(g_gpart + ((size_t)q * BB + cb) * H4 + 4 * ch));
                g4.x += p.x; g4.y += p.y; g4.z += p.z; g4.w += p.w;
            }
            float i = 1.f / (1.f + expf(-g4.x));
            float f = 1.f / (1.f + expf(-g4.y));
            float g = tanhf(g4.z);
            float o = 1.f / (1.f + expf(-g4.w));
            float cx = creg;
            float cy = f * cx + i * g;
            float hy = o * tanhf(cy);
            creg = cy;
            size_t hb = (size_t)cb * HH + ch;
            g_h[(size_t)(t + 1) * BB * HH + hb] = hy;
            out_h[(size_t)t * BB * HH + hb] = hy;
            g_f[(size_t)t * BB * HH + hb] = f;
            size_t db = (size_t)t * BB * H3 + (size_t)cb * H3 + ch;
            g_d[db]          = g * i * (1.f - i);
            g_d[db + HH]     = cx * f * (1.f - f);
            g_d[db + 2 * HH] = i * (1.f - g) * (1.f + g);
            if (t == TT - 1) out_c[hb] = cy;
        }

        // ---- signal cells done ----
        __threadfence();
        __syncthreads();
        if (tid == 0) atomicAdd(&g_cnt_c[t][nt], 1u);
    }
}

// ---------------- reverse suffix-product scan ----------------
__global__ void scan_kernel(float* __restrict__ evb_out) {
    int idx = blockIdx.x * blockDim.x + threadIdx.x;  // < BB*H3
    int b = idx / H3, j = idx % H3;
    int h = j & (HH - 1);
    float p = 1.f, sum = 0.f;
    for (int t = TT - 1; t >= 0; t--) {
        size_t di = (size_t)t * BB * H3 + (size_t)b * H3 + j;
        float w = g_d[di] * p;
        g_d[di] = w;
        sum += w;
        p *= g_f[(size_t)t * BB * HH + (size_t)b * HH + h];
    }
    evb_out[idx] = sum;
}

// ---------------- batched ev GEMM: out[b][j][k] = sum_t w[t][b][j] * Xs[t][b][k] ----------------
// 128x128 tile, 256 threads, acc[16][4]: tj warp-uniform -> A reads broadcast; 1 B LDS per 64 FMA.
__global__ void __launch_bounds__(256, 2)
ev_kernel(const float* __restrict__ Xs, int kdim, float* __restrict__ out) {
    __shared__ __align__(16) float Ws[8][132];
    __shared__ __align__(16) float Bs[8][140];
    if (Xs == nullptr) Xs = g_h;  // ev_hh: h_{t-1} history
    const int tid = threadIdx.x;
    const int b = blockIdx.z;
    const int j0 = blockIdx.y * 128;
    const int k0 = blockIdx.x * 128;
    const int tj = (tid >> 5) * 16;          // warp-uniform j base
    const int tk = (tid & 31) * 4;
    const int pk = PF4(tk >> 2);
    const int ltt = tid >> 5;
    const int lc = tid & 31;
    float acc[16][4] = {};
    for (int t0 = 0; t0 < TT; t0 += 8) {
        int t = t0 + ltt;
        float4 wv = make_float4(0.f, 0.f, 0.f, 0.f);
        float4 xv = make_float4(0.f, 0.f, 0.f, 0.f);
        if (t < TT) {
            wv = *(const float4*)(g_d + (size_t)t * BB * H3 + (size_t)b * H3 + j0 + lc * 4);
            xv = *(const float4*)(Xs + ((size_t)t * BB + b) * kdim + k0 + lc * 4);
        }
        *(float4*)&Ws[ltt][lc * 4] = wv;
        ((float4*)&Bs[ltt][0])[PF4(lc)] = xv;
        __syncthreads();
#pragma unroll
        for (int u = 0; u < 8; u++) {
            float4 a0 = *(const float4*)&Ws[u][tj];        // broadcasts
            float4 a1 = *(const float4*)&Ws[u][tj + 4];
            float4 a2 = *(const float4*)&Ws[u][tj + 8];
            float4 a3 = *(const float4*)&Ws[u][tj + 12];
            float4 bv = ((const float4*)&Bs[u][0])[pk];
            float aa[16] = {a0.x, a0.y, a0.z, a0.w, a1.x, a1.y, a1.z, a1.w,
                            a2.x, a2.y, a2.z, a2.w, a3.x, a3.y, a3.z, a3.w};
#pragma unroll
            for (int i = 0; i < 16; i++) {
                acc[i][0] += aa[i] * bv.x;
                acc[i][1] += aa[i] * bv.y;
                acc[i][2] += aa[i] * bv.z;
                acc[i][3] += aa[i] * bv.w;
            }
        }
        __syncthreads();
    }
#pragma unroll
    for (int i = 0; i < 16; i++) {
        float* orow = out + ((size_t)b * H3 + j0 + tj + i) * kdim + k0 + tk;
        *(float4*)orow = make_float4(acc[i][0], acc[i][1], acc[i][2], acc[i][3]);
    }
}

// ---------------- launch ----------------
extern "C" void kernel_launch(void* const* d_in, const int* in_sizes, int n_in,
                              void* d_out, int out_size) {
    (void)in_sizes; (void)n_in; (void)out_size;
    const float* input = (const float*)d_in[0];
    const float* h0    = (const float*)d_in[1];
    const float* c0    = (const float*)d_in[2];
    const float* wih   = (const float*)d_in[3];
    const float* whh   = (const float*)d_in[4];
    const float* bih   = (const float*)d_in[5];
    const float* bhh   = (const float*)d_in[6];

    float* out         = (float*)d_out;
    float* out_outputs = out;
    float* out_cx      = out_outputs + (size_t)TT * BB * HH;
    float* out_evih    = out_cx + (size_t)BB * HH;
    float* out_evhh    = out_evih + (size_t)BB * H3 * II;
    float* out_evb     = out_evhh + (size_t)BB * H3 * HH;

    prep_kernel<<<512, 256>>>(h0, bih, bhh);
    pack_w<<<dim3(II / 32, H4 / 32), dim3(32, 8)>>>(wih, II, 0);
    pack_w<<<dim3(HH / 32, H4 / 32), dim3(32, 8)>>>(whh, HH, 1);
    gx_kernel<<<dim3(16, 50), 256>>>(input);

    loop_kernel<<<NBLK, 256>>>(c0, out_outputs, out_cx);

    scan_kernel<<<BB * H3 / 256, 256>>>(out_evb);
    ev_kernel<<<dim3(II / 128, H3 / 128, BB), 256>>>(input, II, out_evih);
    ev_kernel<<<dim3(HH / 128, H3 / 128, BB), 256>>>(nullptr, HH, out_evhh);
}

// round 12
// speedup vs baseline: 1.0890x; 1.0890x over previous
#include <cuda_runtime.h>
#include <math.h>

#define TT 100
#define BB 64
#define II 256
#define HH 512
#define H3 1536
#define H4 2048
#define NBLK 128          // persistent grid size (all co-resident)
#define KC 8              // K split chunks (512/64)
#define BKC 64            // K per chunk
#define BROW 284          // swizzled B row floats (71 f4 slots, PF4 max 70)
#define AROW 36           // A row floats (32 m + pad)

#define PF4(x) ((x) + ((x) >> 3))

// ---------------- flag helpers ----------------
// producer: release-add (no separate fence needed)
__device__ __forceinline__ void sig_add(unsigned* p) {
    asm volatile("red.release.gpu.global.add.u32 [%0], 1;" :: "l"(p) : "memory");
}

// ---------------- scratch (device globals) ----------------
__device__ float g_WihP[II * H4];                 // packed: [k][ (n%512)*4 + n/512 ]
__device__ float g_WhhP[HH * H4];
__device__ float g_biasP[H4];
__device__ float g_Gx[(size_t)TT * BB * H4];      // packed gate pre-activations from input path
__device__ float g_h[(size_t)(TT + 1) * BB * HH]; // h history [t][b][h]
__device__ float g_f[(size_t)TT * BB * HH];
__device__ float g_d[(size_t)TT * BB * H3];       // later overwritten with w = d * suffix-prod(f)
__device__ float g_gpart[16 * 32 * H4];           // split-K partials [kcmh][m-local][packed n]
__device__ unsigned g_cnt_g[TT][8];               // partials-done counters per (t, nt)
__device__ unsigned g_cnt_c[TT][8];               // cells-done counters per (t, nt)

// ---------------- prep ----------------
__global__ void prep_kernel(const float* __restrict__ h0, const float* __restrict__ bih,
                            const float* __restrict__ bhh) {
    int i = blockIdx.x * blockDim.x + threadIdx.x;
    if (i < TT * 8) { (&g_cnt_g[0][0])[i] = 0u; (&g_cnt_c[0][0])[i] = 0u; }
    if (i < H4) g_biasP[(i & 511) * 4 + (i >> 9)] = bih[i] + bhh[i];
    if (i < BB * HH) g_h[i] = h0[i];
}

// ---------------- pack weights: in[2048][K] -> out[K][2048 packed] ----------------
__global__ void pack_w(const float* __restrict__ in, int K, int which) {
    __shared__ float s[32][33];
    int k0 = blockIdx.x * 32, n0 = blockIdx.y * 32;
    int tx = threadIdx.x, ty = threadIdx.y;
    for (int i = ty; i < 32; i += 8)
        s[i][tx] = in[(size_t)(n0 + i) * K + k0 + tx];
    __syncthreads();
    float* out = which ? g_WhhP : g_WihP;
    int g = n0 >> 9;
    int c = n0 & 511;
    for (int i = ty; i < 32; i += 8)
        out[(size_t)(k0 + i) * H4 + (c + tx) * 4 + g] = s[tx][i];
}

// ---------------- Gx = X[6400,256] @ WihP + biasP (packed out), acc[16][4] ev-style ----------------
// 128x128 tile, 256 threads; warps = 8 m-groups of 16 (warp-uniform), lanes cover 32 n-f4.
// Per u: 4 broadcast A LDS.128 + 1 conflict-free B LDS.128 + 64 FFMA.
__global__ void __launch_bounds__(256, 2) gx_kernel(const float* __restrict__ X) {
    __shared__ __align__(16) float As[8][132];
    __shared__ __align__(16) float Bs[8][140];    // 35 f4 slots (PF4 max 34)
    const int tid = threadIdx.x;
    const int n0 = blockIdx.x * 128;
    const int m0 = blockIdx.y * 128;
    const int tj = (tid >> 5) * 16;               // warp-uniform m base
    const int tk = (tid & 31) * 4;                // n within tile
    const int pk = PF4(tid & 31);
    const int am = tid >> 1, ak = (tid & 1) * 4;  // A staging: 128 m x 2 k-quads
    const int bk = tid >> 5, bn_f4 = tid & 31;    // B staging
    float acc[16][4] = {};
    for (int k0 = 0; k0 < II; k0 += 8) {
        float4 av = *(const float4*)(X + (size_t)(m0 + am) * II + k0 + ak);
        As[ak + 0][am] = av.x; As[ak + 1][am] = av.y; As[ak + 2][am] = av.z; As[ak + 3][am] = av.w;
        ((float4*)&Bs[bk][0])[PF4(bn_f4)] = *(const float4*)(g_WihP + (size_t)(k0 + bk) * H4 + n0 + bn_f4 * 4);
        __syncthreads();
#pragma unroll
        for (int u = 0; u < 8; u++) {
            float4 a0 = *(const float4*)&As[u][tj];       // broadcasts
            float4 a1 = *(const float4*)&As[u][tj + 4];
            float4 a2 = *(const float4*)&As[u][tj + 8];
            float4 a3 = *(const float4*)&As[u][tj + 12];
            float4 bv = ((const float4*)&Bs[u][0])[pk];
            float aa[16] = {a0.x, a0.y, a0.z, a0.w, a1.x, a1.y, a1.z, a1.w,
                            a2.x, a2.y, a2.z, a2.w, a3.x, a3.y, a3.z, a3.w};
#pragma unroll
            for (int i = 0; i < 16; i++) {
                acc[i][0] += aa[i] * bv.x;
                acc[i][1] += aa[i] * bv.y;
                acc[i][2] += aa[i] * bv.z;
                acc[i][3] += aa[i] * bv.w;
            }
        }
        __syncthreads();
    }
    float4 bias4 = *(const float4*)(g_biasP + n0 + tk);
#pragma unroll
    for (int i = 0; i < 16; i++) {
        float* orow = g_Gx + (size_t)(m0 + tj + i) * H4 + n0 + tk;
        *(float4*)orow = make_float4(acc[i][0] + bias4.x, acc[i][1] + bias4.y,
                                     acc[i][2] + bias4.z, acc[i][3] + bias4.w);
    }
}

// ---------------- persistent recurrent loop: R9-proven split-K (KC=8, M-split 2) ----------------
// 128 blocks x 256 threads. Block (nt 0..7, kc 0..7, mh 0..1):
//   GEMM tile M=32 (batch rows mh*32..+32), N=256 packed (nt), K=64 (kc).
// Cell: block handles b in [kcmh*4, +4) x h-cols [nt*64, +64); c state in register.
__global__ void __launch_bounds__(256, 1)
loop_kernel(const float* __restrict__ c0, float* __restrict__ out_h, float* __restrict__ out_c) {
    extern __shared__ float smdyn[];
    float* Bsm = smdyn;                  // [64][BROW]  (~72.7 KB)
    float* Asm = smdyn + 64 * BROW;      // [64][AROW]  (~9.2 KB)

    const int tid = threadIdx.x;
    const int nt = blockIdx.x & 7;
    const int kcmh = blockIdx.x >> 3;    // 0..15
    const int kc = kcmh >> 1;            // 0..7
    const int mh = kcmh & 1;             // 0..1
    const int n0 = nt * 256;
    const int k0 = kc * BKC;
    const int m0 = mh * 32;

    // stage weight chunk once (swizzled): 64k x 64 f4
    {
        const float* wsrc = g_WhhP + (size_t)k0 * H4 + n0;
#pragma unroll
        for (int r = 0; r < 16; r++) {
            int e = r * 256 + tid;
            int kk = e >> 6;
            int nf4 = e & 63;
            ((float4*)(Bsm + kk * BROW))[PF4(nf4)] = *(const float4*)(wsrc + (size_t)kk * H4 + nf4 * 4);
        }
    }

    const int tm = (tid >> 5) * 4;           // warp-uniform m (broadcast A reads), 0..28
    const int tn = (tid & 31) * 8;
    const int pn0 = PF4(tn >> 2);
    const int pn1 = PF4((tn >> 2) + 1);
    const int am = tid >> 3, ak = (tid & 7) * 8;   // A load map: 32 m rows x 8 k-octs

    // cell identity (fixed all steps)
    const int cb = kcmh * 4 + (tid >> 6);    // batch
    const int ch = nt * 64 + (tid & 63);     // global h col
    float creg = c0[(size_t)cb * HH + ch];

    for (int t = 0; t < TT; t++) {
        // ---- wait for h[t] producers (skip t=0: prep wrote it). nt_src = kc. ----
        if (t > 0) {
            if (tid == 0) {
                volatile unsigned* p = &g_cnt_c[t - 1][kc];
                while (*p < 16u) __nanosleep(64);
                __threadfence();
            }
            __syncthreads();
        }

        // ---- load A chunk: h[t][m0..m0+32)[k0..k0+64) -> Asm[k][m] ----
        const float* hsrc = g_h + (size_t)t * BB * HH;
        float4 v0 = __ldcg((const float4*)(hsrc + (size_t)(m0 + am) * HH + k0 + ak));
        float4 v1 = __ldcg((const float4*)(hsrc + (size_t)(m0 + am) * HH + k0 + ak + 4));
        Asm[(ak + 0) * AROW + am] = v0.x; Asm[(ak + 1) * AROW + am] = v0.y;
        Asm[(ak + 2) * AROW + am] = v0.z; Asm[(ak + 3) * AROW + am] = v0.w;
        Asm[(ak + 4) * AROW + am] = v1.x; Asm[(ak + 5) * AROW + am] = v1.y;
        Asm[(ak + 6) * AROW + am] = v1.z; Asm[(ak + 7) * AROW + am] = v1.w;

        // prefetch this step's Gx for the cell (independent of GEMM)
        float4 gx4 = __ldcg((const float4*)(g_Gx + ((size_t)t * BB + cb) * H4 + 4 * ch));
        __syncthreads();

        // ---- GEMM 32x256, K=64 ----
        float acc[4][8] = {};
#pragma unroll 16
        for (int u = 0; u < BKC; u++) {
            float4 a = *(const float4*)(Asm + u * AROW + tm);   // broadcast
            float4 b0 = ((const float4*)(Bsm + u * BROW))[pn0];
            float4 b1 = ((const float4*)(Bsm + u * BROW))[pn1];
            float aa[4] = {a.x, a.y, a.z, a.w};
            float bb[8] = {b0.x, b0.y, b0.z, b0.w, b1.x, b1.y, b1.z, b1.w};
#pragma unroll
            for (int i = 0; i < 4; i++)
#pragma unroll
                for (int j = 0; j < 8; j++)
                    acc[i][j] += aa[i] * bb[j];
        }
#pragma unroll
        for (int i = 0; i < 4; i++) {
            float* prow = g_gpart + ((size_t)kcmh * 32 + tm + i) * H4 + n0 + tn;
            *(float4*)prow = make_float4(acc[i][0], acc[i][1], acc[i][2], acc[i][3]);
            *(float4*)(prow + 4) = make_float4(acc[i][4], acc[i][5], acc[i][6], acc[i][7]);
        }

        // ---- signal partials done (release-add), wait for all 16 producers of our nt ----
        __syncthreads();                      // Asm also reused next step; orders warps pre-signal
        if (tid == 0) {
            sig_add(&g_cnt_g[t][nt]);
            volatile unsigned* p = &g_cnt_g[t][nt];
            while (*p < 16u) __nanosleep(64);
            __threadfence();
        }
        __syncthreads();

        // ---- cell for (cb, ch): sum 8 partials (kc 0..7, mh = cb>>5) ----
        {
            float4 g4 = gx4;
#pragma unroll
            for (int q = 0; q < KC; q++) {
                int pk = q * 2 + (cb >> 5);
                float4 p = __ldcg((const float4*)(g_gpart + ((size_t)pk * 32 + (cb & 31)) * H4 + 4 * ch));
                g4.x += p.x; g4.y += p.y; g4.z += p.z; g4.w += p.w;
            }
            float i = 1.f / (1.f + expf(-g4.x));
            float f = 1.f / (1.f + expf(-g4.y));
            float g = tanhf(g4.z);
            float o = 1.f / (1.f + expf(-g4.w));
            float cx = creg;
            float cy = f * cx + i * g;
            float hy = o * tanhf(cy);
            creg = cy;
            size_t hb = (size_t)cb * HH + ch;
            g_h[(size_t)(t + 1) * BB * HH + hb] = hy;
            out_h[(size_t)t * BB * HH + hb] = hy;
            g_f[(size_t)t * BB * HH + hb] = f;
            size_t db = (size_t)t * BB * H3 + (size_t)cb * H3 + ch;
            g_d[db]          = g * i * (1.f - i);
            g_d[db + HH]     = cx * f * (1.f - f);
            g_d[db + 2 * HH] = i * (1.f - g) * (1.f + g);
            if (t == TT - 1) out_c[hb] = cy;
        }

        // ---- signal cells done (release-add) ----
        __syncthreads();
        if (tid == 0) sig_add(&g_cnt_c[t][nt]);
    }
}

// ---------------- reverse suffix-product scan ----------------
__global__ void scan_kernel(float* __restrict__ evb_out) {
    int idx = blockIdx.x * blockDim.x + threadIdx.x;  // < BB*H3
    int b = idx / H3, j = idx % H3;
    int h = j & (HH - 1);
    float p = 1.f, sum = 0.f;
    for (int t = TT - 1; t >= 0; t--) {
        size_t di = (size_t)t * BB * H3 + (size_t)b * H3 + j;
        float w = g_d[di] * p;
        g_d[di] = w;
        sum += w;
        p *= g_f[(size_t)t * BB * HH + (size_t)b * HH + h];
    }
    evb_out[idx] = sum;
}

// ---------------- batched ev GEMM: out[b][j][k] = sum_t w[t][b][j] * Xs[t][b][k] ----------------
// 128x128 tile, 256 threads, acc[16][4]: tj warp-uniform -> A reads broadcast; 1 B LDS per 64 FMA.
__global__ void __launch_bounds__(256, 2)
ev_kernel(const float* __restrict__ Xs, int kdim, float* __restrict__ out) {
    __shared__ __align__(16) float Ws[8][132];
    __shared__ __align__(16) float Bs[8][140];
    if (Xs == nullptr) Xs = g_h;  // ev_hh: h_{t-1} history
    const int tid = threadIdx.x;
    const int b = blockIdx.z;
    const int j0 = blockIdx.y * 128;
    const int k0 = blockIdx.x * 128;
    const int tj = (tid >> 5) * 16;          // warp-uniform j base
    const int tk = (tid & 31) * 4;
    const int pk = PF4(tk >> 2);
    const int ltt = tid >> 5;
    const int lc = tid & 31;
    float acc[16][4] = {};
    for (int t0 = 0; t0 < TT; t0 += 8) {
        int t = t0 + ltt;
        float4 wv = make_float4(0.f, 0.f, 0.f, 0.f);
        float4 xv = make_float4(0.f, 0.f, 0.f, 0.f);
        if (t < TT) {
            wv = *(const float4*)(g_d + (size_t)t * BB * H3 + (size_t)b * H3 + j0 + lc * 4);
            xv = *(const float4*)(Xs + ((size_t)t * BB + b) * kdim + k0 + lc * 4);
        }
        *(float4*)&Ws[ltt][lc * 4] = wv;
        ((float4*)&Bs[ltt][0])[PF4(lc)] = xv;
        __syncthreads();
#pragma unroll
        for (int u = 0; u < 8; u++) {
            float4 a0 = *(const float4*)&Ws[u][tj];        // broadcasts
            float4 a1 = *(const float4*)&Ws[u][tj + 4];
            float4 a2 = *(const float4*)&Ws[u][tj + 8];
            float4 a3 = *(const float4*)&Ws[u][tj + 12];
            float4 bv = ((const float4*)&Bs[u][0])[pk];
            float aa[16] = {a0.x, a0.y, a0.z, a0.w, a1.x, a1.y, a1.z, a1.w,
                            a2.x, a2.y, a2.z, a2.w, a3.x, a3.y, a3.z, a3.w};
#pragma unroll
            for (int i = 0; i < 16; i++) {
                acc[i][0] += aa[i] * bv.x;
                acc[i][1] += aa[i] * bv.y;
                acc[i][2] += aa[i] * bv.z;
                acc[i][3] += aa[i] * bv.w;
            }
        }
        __syncthreads();
    }
#pragma unroll
    for (int i = 0; i < 16; i++) {
        float* orow = out + ((size_t)b * H3 + j0 + tj + i) * kdim + k0 + tk;
        *(float4*)orow = make_float4(acc[i][0], acc[i][1], acc[i][2], acc[i][3]);
    }
}

// ---------------- launch ----------------
extern "C" void kernel_launch(void* const* d_in, const int* in_sizes, int n_in,
                              void* d_out, int out_size) {
    (void)in_sizes; (void)n_in; (void)out_size;
    const float* input = (const float*)d_in[0];
    const float* h0    = (const float*)d_in[1];
    const float* c0    = (const float*)d_in[2];
    const float* wih   = (const float*)d_in[3];
    const float* whh   = (const float*)d_in[4];
    const float* bih   = (const float*)d_in[5];
    const float* bhh   = (const float*)d_in[6];

    float* out         = (float*)d_out;
    float* out_outputs = out;
    float* out_cx      = out_outputs + (size_t)TT * BB * HH;
    float* out_evih    = out_cx + (size_t)BB * HH;
    float* out_evhh    = out_evih + (size_t)BB * H3 * II;
    float* out_evb     = out_evhh + (size_t)BB * H3 * HH;

    const int loop_smem = (64 * BROW + 64 * AROW) * 4;   // ~82 KB
    cudaFuncSetAttribute(loop_kernel, cudaFuncAttributeMaxDynamicSharedMemorySize, loop_smem);

    prep_kernel<<<512, 256>>>(h0, bih, bhh);
    pack_w<<<dim3(II / 32, H4 / 32), dim3(32, 8)>>>(wih, II, 0);
    pack_w<<<dim3(HH / 32, H4 / 32), dim3(32, 8)>>>(whh, HH, 1);
    gx_kernel<<<dim3(16, 50), 256>>>(input);

    loop_kernel<<<NBLK, 256, loop_smem>>>(c0, out_outputs, out_cx);

    scan_kernel<<<BB * H3 / 256, 256>>>(out_evb);
    ev_kernel<<<dim3(II / 128, H3 / 128, BB), 256>>>(input, II, out_evih);
    ev_kernel<<<dim3(HH / 128, H3 / 128, BB), 256>>>(nullptr, HH, out_evhh);
}